// round 15
// baseline (speedup 1.0000x reference)
#include <cuda_runtime.h>
#include <math.h>

#define N_ROWS   16384
#define ACTIONS  64
#define EMB      32
#define DELTA    16
#define EPSF     1e-5f

#define NB1      64                      // bn_partial blocks
#define ROWS_PER_B1 (N_ROWS / NB1)       // 256

#define A_PER_B  4                       // actions per spline block
#define R_PER_B  128                     // rows per spline block
#define NBINS    33                      // staged bins (bl 0..31, bh needs +1)

// Scratch: BN partial sums (no allocation allowed in kernel_launch).
__device__ float g_psum[NB1][ACTIONS];
__device__ float g_psq [NB1][ACTIONS];

// ---------------------------------------------------------------------------
// Kernel 1: per-block partial sum/sumsq per action column. 64 blocks x 256
// rows (2x the SM parallelism of the previous 32-block version). float4
// loads in explicit 8-deep batches (MLP=8). Deterministic.
// ---------------------------------------------------------------------------
__global__ __launch_bounds__(256) void bn_partial(const float* __restrict__ x)
{
    const int tid = threadIdx.x;
    const int c4  = tid & 15;
    const int r   = tid >> 4;
    const int b   = blockIdx.x;

    const float4* px = reinterpret_cast<const float4*>(x)
                     + (size_t)(b * ROWS_PER_B1 + r) * (ACTIONS / 4) + c4;

    float4 s = {0.f, 0.f, 0.f, 0.f};
    float4 q = {0.f, 0.f, 0.f, 0.f};
#pragma unroll
    for (int m = 0; m < 2; m++) {
        float4 v[8];
#pragma unroll
        for (int k = 0; k < 8; k++)
            v[k] = __ldg(px + (size_t)(m * 8 + k) * 16 * (ACTIONS / 4));
#pragma unroll
        for (int k = 0; k < 8; k++) {
            s.x += v[k].x; q.x += v[k].x * v[k].x;
            s.y += v[k].y; q.y += v[k].y * v[k].y;
            s.z += v[k].z; q.z += v[k].z * v[k].z;
            s.w += v[k].w; q.w += v[k].w * v[k].w;
        }
    }

    __shared__ float4 ss[16][16];
    __shared__ float4 sq[16][16];
    ss[r][c4] = s;
    sq[r][c4] = q;
    __syncthreads();

    if (tid < ACTIONS) {
        const int c = tid, cc = c >> 2, ce = c & 3;
        float ts = 0.f, tq = 0.f;
#pragma unroll
        for (int r2 = 0; r2 < 16; r2++) {
            ts += reinterpret_cast<const float*>(&ss[r2][cc])[ce];
            tq += reinterpret_cast<const float*>(&sq[r2][cc])[ce];
        }
        g_psum[b][c] = ts;
        g_psq [b][c] = tq;
    }
}

// ---------------------------------------------------------------------------
// Kernel 2 (fused): BN prologue + smem-staged spline, v6.
// Identical per-pair op structure to v5 (2 LDS.128 + 1 STG.128 + 1 SHFL per
// 4 pairs; 22 MIO cyc -> 22.3us/SM ideal). v5 measured 27.7us at occ=64.6%
// because grid=1024 underfills the chip (6.9 blocks/SM vs 8 resident) with a
// ragged tail. v6: R_PER_B 128 -> grid 2048 -> 8 blocks/SM, ~1.7 packed
// waves. Occupancy experiment: if latency-hiding is the gap, spline -> ~24;
// if flat, the MIO floor is structural.
//  - 16.9KB staged table slice; bh = bin+1 row (xh = xl+1 always).
//  - lane (g,e4) precomputes F[m] = f(row0+8m+e4, a0+g), m=0..1 (16 rows per
//    warp now); iter jb=8m+i: fj = shfl(F[m], g*8+i), compile-time m.
//  - one STG.128 of 512B contiguous output per warp-iter (__stcs).
//  - Deterministic: fixed-order butterfly prologue, bit-identical per block.
// ---------------------------------------------------------------------------
__global__ __launch_bounds__(256) void spline_v6(const float* __restrict__ x,
                                                 const float* __restrict__ emb,
                                                 const float* __restrict__ wgt,
                                                 const float* __restrict__ bias,
                                                 float* __restrict__ out)
{
    __shared__ __align__(16) float s_tab[NBINS * A_PER_B * EMB]; // [bin][a][e]
    __shared__ float s_sc[A_PER_B];
    __shared__ float s_sh[A_PER_B];

    const int tid  = threadIdx.x;
    const int lane = tid & 31;
    const int w    = tid >> 5;                 // warp 0..7
    const int a0   = blockIdx.y * A_PER_B;
    const int row0 = blockIdx.x * R_PER_B + w * 16;

    // ---- BN finalize: 4 actions x 64 partials (fold 2, butterfly 32) ----
    if (tid < 128) {
        const int ai = tid >> 5;
        const int p  = tid & 31;
        float s = g_psum[p][a0 + ai] + g_psum[p + 32][a0 + ai];
        float q = g_psq [p][a0 + ai] + g_psq [p + 32][a0 + ai];
#pragma unroll
        for (int off = 16; off > 0; off >>= 1) {
            s += __shfl_xor_sync(0xffffffffu, s, off);
            q += __shfl_xor_sync(0xffffffffu, q, off);
        }
        if (p == 0) {
            const float inv_n = 1.0f / (float)N_ROWS;
            float mean = s * inv_n;
            float var  = fmaf(-mean, mean, q * inv_n);
            float sc   = wgt[a0 + ai] * rsqrtf(var + EPSF);
            s_sc[ai] = sc;
            s_sh[ai] = fmaf(-mean, sc, bias[a0 + ai]);
        }
    }

    // ---- stage table slice: bins 0..32, this block's 4 actions ----
    {
        float4* st4 = reinterpret_cast<float4*>(s_tab);
        const float4* e4p = reinterpret_cast<const float4*>(emb);
        // 33*4*8 = 1056 float4
        for (int i = tid; i < NBINS * A_PER_B * 8; i += 256) {
            const int bin = i >> 5;            // /32
            const int a   = (i >> 3) & 3;
            const int e4  = i & 7;
            st4[i] = __ldg(e4p + ((size_t)bin * ACTIONS + a0 + a) * 8 + e4);
        }
    }
    __syncthreads();

    const int g  = lane >> 3;                  // pair group 0..3 (action)
    const int e4 = lane & 7;                   // float4 slot within EMB
    const int g8 = g << 3;

    // ---- prologue: 2 scalar x loads + 2 tanh in F-layout ----
    // F[m] = f(row0 + 8m + e4, a0 + g)
    const float sc = s_sc[g];
    const float sh = s_sh[g];
    float F[2];
    {
        const float* xp = x + (size_t)(row0 + e4) * ACTIONS + a0 + g;
        float xv[2];
#pragma unroll
        for (int m = 0; m < 2; m++)
            xv[m] = __ldg(xp + (size_t)m * 8 * ACTIONS);
#pragma unroll
        for (int m = 0; m < 2; m++) {
            float t = tanhf(fmaf(xv[m], sc, sh));
            t = fminf(fmaxf(t, -1.0f + 1e-5f), 1.0f - 1e-5f);
            F[m] = t * (float)DELTA;           // exact pow2 scale
        }
    }

    const float4* tab4 = reinterpret_cast<const float4*>(s_tab);
    float4* out4 = reinterpret_cast<float4*>(out) + (size_t)g8 + e4;

    // ---- main loop: 16 rows/warp, one row (4 pairs) per iter, full unroll ----
#pragma unroll
    for (int m = 0; m < 2; m++) {
#pragma unroll
        for (int i = 0; i < 8; i++) {
            const int jb = m * 8 + i;
            const float fj = __shfl_sync(0xffffffffu, F[m], g8 + i);

            const float xlf = floorf(fj);
            const float wh  = fj - xlf;        // = DELTA*(t-xl), exact
            const float wl  = 1.0f - wh;       // = DELTA*(xh-t)
            const int   bin = (int)xlf + DELTA;    // 0..31

            const float4* p = tab4 + ((bin * A_PER_B + g) << 3) + e4;
            const float4 bl = p[0];
            const float4 bh = p[A_PER_B * 8];  // bin+1: +4 actions * 8 f4

            float4 h;
            h.x = bh.x * wh + bl.x * wl;
            h.y = bh.y * wh + bl.y * wl;
            h.z = bh.z * wh + bl.z * wl;
            h.w = bh.w * wh + bl.w * wl;

            // 32 lanes -> 512B contiguous: (row, a0..a0+3, all EMB)
            __stcs(out4 + ((size_t)(row0 + jb) * ACTIONS + a0) * 8, h);
        }
    }
}

// ---------------------------------------------------------------------------
// Launch: x, bn_weight, bn_bias, emb_table  ->  out [n, ACTIONS, EMB] fp32
// ---------------------------------------------------------------------------
extern "C" void kernel_launch(void* const* d_in, const int* in_sizes, int n_in,
                              void* d_out, int out_size)
{
    const float* x    = (const float*)d_in[0];
    const float* wgt  = (const float*)d_in[1];
    const float* bias = (const float*)d_in[2];
    const float* emb  = (const float*)d_in[3];
    float* out        = (float*)d_out;

    bn_partial<<<NB1, 256>>>(x);

    dim3 grid(N_ROWS / R_PER_B, ACTIONS / A_PER_B);   // (128, 16)
    spline_v6<<<grid, 256>>>(x, emb, wgt, bias, out);
}